// round 1
// baseline (speedup 1.0000x reference)
#include <cuda_runtime.h>
#include <math.h>

#define NFEAT 64
#define DIM   256
#define NHEAD 8
#define HDIM  32
#define XS    258   // padded row stride (floats) for xs/qs/ks
#define ATS   65    // padded row stride for att

// smem float layout:
//   xs : 64*258      q/k inputs + residual
//   qs : 64*258
//   ks : 64*258
//   att: 64*65
//   kt : 2048        transposed k-head; reused as z-head (zh)
//   vh : 2048
//   red: 256
#define SMEM_FLOATS (3*NFEAT*XS + NFEAT*ATS + 2048 + 2048 + 256)

// Full 64x256 = x @ W + b GEMM into padded smem buffer.
// Thread tile: jg = t&63 -> 4 consecutive cols (float4 W loads), i0 = (t>>6)*16 -> 16 rows.
__device__ __forceinline__
void gemm_qk(const float* __restrict__ W, const float* __restrict__ bias,
             const float* xs, float* os, int t)
{
    const int jg = t & 63;
    const int i0 = (t >> 6) << 4;
    const float4* W4 = (const float4*)W;
    float acc[16][4];
#pragma unroll
    for (int r = 0; r < 16; r++) { acc[r][0]=0.f; acc[r][1]=0.f; acc[r][2]=0.f; acc[r][3]=0.f; }
#pragma unroll 2
    for (int k = 0; k < DIM; k++) {
        float4 w = W4[(k << 6) + jg];
#pragma unroll
        for (int r = 0; r < 16; r++) {
            float xv = xs[(i0 + r) * XS + k];
            acc[r][0] += xv * w.x;
            acc[r][1] += xv * w.y;
            acc[r][2] += xv * w.z;
            acc[r][3] += xv * w.w;
        }
    }
    float4 bb = ((const float4*)bias)[jg];
    const int j0 = jg << 2;
#pragma unroll
    for (int r = 0; r < 16; r++) {
        float* d = os + (i0 + r) * XS + j0;
        d[0] = acc[r][0] + bb.x;
        d[1] = acc[r][1] + bb.y;
        d[2] = acc[r][2] + bb.z;
        d[3] = acc[r][3] + bb.w;
    }
}

__global__ __launch_bounds__(256, 1)
void autoint_kernel(const float* __restrict__ x,
                    const float* __restrict__ Wq, const float* __restrict__ bq,
                    const float* __restrict__ Wk, const float* __restrict__ bk,
                    const float* __restrict__ Wv, const float* __restrict__ bv,
                    const float* __restrict__ W1, const float* __restrict__ b1,
                    const float* __restrict__ W2, const float* __restrict__ b2,
                    float* __restrict__ out)
{
    extern __shared__ float sm[];
    float* xs  = sm;                    // 64*258
    float* qs  = xs + NFEAT * XS;
    float* ks  = qs + NFEAT * XS;
    float* att = ks + NFEAT * XS;       // 64*65
    float* kt  = att + NFEAT * ATS;     // 2048, reused as zh
    float* vh  = kt + 2048;             // 2048
    float* red = vh + 2048;             // 256

    const int t = threadIdx.x;
    const int b = blockIdx.x;
    const float* xg = x + (size_t)b * (NFEAT * DIM);

    // ---- load x into padded smem ----
    {
        const float4* xg4 = (const float4*)xg;
#pragma unroll
        for (int n = t; n < NFEAT * DIM / 4; n += 256) {
            float4 v = xg4[n];
            int row = n >> 6;
            int c4  = (n & 63) << 2;
            float* d = xs + row * XS + c4;
            d[0] = v.x; d[1] = v.y; d[2] = v.z; d[3] = v.w;
        }
    }
    __syncthreads();

    // ---- q, k projections (full 64x256 GEMMs) ----
    gemm_qk(Wq, bq, xs, qs, t);
    gemm_qk(Wk, bk, xs, ks, t);
    __syncthreads();

    const float inv_sqrt_d = 0.17677669529663687f; // 1/sqrt(32)

    // f accumulator in registers; same (jg, i0) mapping as gemm_qk
    float facc[16][4];
#pragma unroll
    for (int r = 0; r < 16; r++) { facc[r][0]=0.f; facc[r][1]=0.f; facc[r][2]=0.f; facc[r][3]=0.f; }

    for (int h = 0; h < NHEAD; h++) {
        const int hd = h * HDIM;

        // ---- transpose k head: kt[kk][j] = ks[j][hd+kk] ----
#pragma unroll
        for (int n = t; n < HDIM * NFEAT; n += 256) {
            int kk = n >> 6, j = n & 63;
            kt[n] = ks[j * XS + hd + kk];
        }
        __syncthreads();

        // ---- attention scores: att[i][j] = q_h[i] . k_h[j] / sqrt(32) ----
        {
            const int i0 = (t >> 4) << 2;       // 4 rows
            const int j0 = (t & 15) << 2;       // 4 cols
            float a[4][4];
#pragma unroll
            for (int r = 0; r < 4; r++) { a[r][0]=0.f; a[r][1]=0.f; a[r][2]=0.f; a[r][3]=0.f; }
#pragma unroll 4
            for (int kk = 0; kk < HDIM; kk++) {
                float4 kv = *(const float4*)&kt[(kk << 6) + j0];
#pragma unroll
                for (int r = 0; r < 4; r++) {
                    float qv = qs[(i0 + r) * XS + hd + kk];
                    a[r][0] += qv * kv.x;
                    a[r][1] += qv * kv.y;
                    a[r][2] += qv * kv.z;
                    a[r][3] += qv * kv.w;
                }
            }
#pragma unroll
            for (int r = 0; r < 4; r++) {
                float* d = att + (i0 + r) * ATS + j0;
                d[0] = a[r][0] * inv_sqrt_d;
                d[1] = a[r][1] * inv_sqrt_d;
                d[2] = a[r][2] * inv_sqrt_d;
                d[3] = a[r][3] * inv_sqrt_d;
            }
        }

        // ---- v head: vh = x @ Wv[:, hd:hd+32] + bv ----
        {
            const int dv0 = (t & 7) << 2;       // 4 cols of head-v
            const int i0  = (t >> 3) << 1;      // 2 rows
            float a[2][4];
#pragma unroll
            for (int r = 0; r < 2; r++) { a[r][0]=0.f; a[r][1]=0.f; a[r][2]=0.f; a[r][3]=0.f; }
#pragma unroll 8
            for (int k = 0; k < DIM; k++) {
                float4 w = *(const float4*)&Wv[k * DIM + hd + dv0];
#pragma unroll
                for (int r = 0; r < 2; r++) {
                    float xv = xs[(i0 + r) * XS + k];
                    a[r][0] += xv * w.x;
                    a[r][1] += xv * w.y;
                    a[r][2] += xv * w.z;
                    a[r][3] += xv * w.w;
                }
            }
            float4 bb = *(const float4*)&bv[hd + dv0];
#pragma unroll
            for (int r = 0; r < 2; r++) {
                float* d = vh + (i0 + r) * HDIM + dv0;
                d[0] = a[r][0] + bb.x;
                d[1] = a[r][1] + bb.y;
                d[2] = a[r][2] + bb.z;
                d[3] = a[r][3] + bb.w;
            }
        }
        __syncthreads();

        // ---- softmax over j (one row per thread, t < 64) ----
        if (t < NFEAT) {
            float* row = att + t * ATS;
            float m = row[0];
#pragma unroll
            for (int j = 1; j < NFEAT; j++) m = fmaxf(m, row[j]);
            float s = 0.f;
#pragma unroll
            for (int j = 0; j < NFEAT; j++) { float e = __expf(row[j] - m); row[j] = e; s += e; }
            float inv = 1.f / s;
#pragma unroll
            for (int j = 0; j < NFEAT; j++) row[j] *= inv;
        }
        __syncthreads();

        // ---- z head: zh = att @ vh  (zh reuses kt buffer) ----
        float* zh = kt;
        {
            const int dv0 = (t & 15) << 1;      // 2 cols
            const int i0  = (t >> 4) << 2;      // 4 rows
            float a[4][2];
#pragma unroll
            for (int r = 0; r < 4; r++) { a[r][0]=0.f; a[r][1]=0.f; }
#pragma unroll 4
            for (int j = 0; j < NFEAT; j++) {
                float2 vv = *(const float2*)&vh[j * HDIM + dv0];
#pragma unroll
                for (int r = 0; r < 4; r++) {
                    float av = att[(i0 + r) * ATS + j];
                    a[r][0] += av * vv.x;
                    a[r][1] += av * vv.y;
                }
            }
#pragma unroll
            for (int r = 0; r < 4; r++) {
                zh[(i0 + r) * HDIM + dv0]     = a[r][0];
                zh[(i0 + r) * HDIM + dv0 + 1] = a[r][1];
            }
        }
        __syncthreads();

        // ---- facc += z_h @ W1[hd:hd+32, :] ----
        {
            const int jg = t & 63;
            const int i0 = (t >> 6) << 4;
            const float4* W14 = (const float4*)W1;
#pragma unroll 2
            for (int kk = 0; kk < HDIM; kk++) {
                float4 w = W14[((hd + kk) << 6) + jg];
#pragma unroll
                for (int r = 0; r < 16; r++) {
                    float zv = zh[(i0 + r) * HDIM + kk];
                    facc[r][0] += zv * w.x;
                    facc[r][1] += zv * w.y;
                    facc[r][2] += zv * w.z;
                    facc[r][3] += zv * w.w;
                }
            }
        }
        __syncthreads();  // protect zh (kt) before next head rewrites it
    }

    // ---- f = relu(facc + b1 + x); partial = sum f * W2 ----
    {
        const int jg = t & 63;
        const int i0 = (t >> 6) << 4;
        const int j0 = jg << 2;
        float4 b1v = ((const float4*)b1)[jg];
        float part = 0.f;
#pragma unroll
        for (int r = 0; r < 16; r++) {
            int i = i0 + r;
            float4 w2 = ((const float4*)W2)[(i << 6) + jg];
            float f0 = fmaxf(facc[r][0] + b1v.x + xs[i * XS + j0],     0.f);
            float f1 = fmaxf(facc[r][1] + b1v.y + xs[i * XS + j0 + 1], 0.f);
            float f2 = fmaxf(facc[r][2] + b1v.z + xs[i * XS + j0 + 2], 0.f);
            float f3 = fmaxf(facc[r][3] + b1v.w + xs[i * XS + j0 + 3], 0.f);
            part += f0 * w2.x + f1 * w2.y + f2 * w2.z + f3 * w2.w;
        }
        red[t] = part;
    }
    __syncthreads();

    // ---- block reduce + sigmoid ----
#pragma unroll
    for (int s = 128; s > 0; s >>= 1) {
        if (t < s) red[t] += red[t + s];
        __syncthreads();
    }
    if (t == 0) {
        float logit = red[0] + b2[0];
        out[b] = 1.f / (1.f + __expf(-logit));
    }
}

extern "C" void kernel_launch(void* const* d_in, const int* in_sizes, int n_in,
                              void* d_out, int out_size)
{
    const float* x  = (const float*)d_in[0];
    const float* Wq = (const float*)d_in[1];
    const float* bq = (const float*)d_in[2];
    const float* Wk = (const float*)d_in[3];
    const float* bk = (const float*)d_in[4];
    const float* Wv = (const float*)d_in[5];
    const float* bv = (const float*)d_in[6];
    const float* W1 = (const float*)d_in[7];
    const float* b1 = (const float*)d_in[8];
    const float* W2 = (const float*)d_in[9];
    const float* b2 = (const float*)d_in[10];
    float* out = (float*)d_out;

    const int smem_bytes = SMEM_FLOATS * (int)sizeof(float); // 232192 <= 232448
    cudaFuncSetAttribute(autoint_kernel,
                         cudaFuncAttributeMaxDynamicSharedMemorySize, smem_bytes);

    autoint_kernel<<<8192, 256, smem_bytes>>>(x, Wq, bq, Wk, bk, Wv, bv,
                                              W1, b1, W2, b2, out);
}

// round 2
// speedup vs baseline: 1.1315x; 1.1315x over previous
#include <cuda_runtime.h>
#include <math.h>

#define NFEAT 64
#define DIM   256
#define NHEAD 8
#define HDIM  32
#define XS    260   // padded x row stride (floats); 260*4B % 16 == 0 -> float4 rows
#define QS    36    // qh row stride
#define ATS   68    // att row stride

// smem floats:
//  xs  64*260 = 16640
//  qh  64*36  =  2304
//  kt  32*64  =  2048   (k transposed; reused as zh 64*32)
//  vh  64*32  =  2048
//  att 64*68  =  4352
//  red          256
#define SMEM_FLOATS (NFEAT*XS + NFEAT*QS + 2048 + 2048 + NFEAT*ATS + 256)

// Per-head projection: out[64 x 32] = xs @ W[:, hd:hd+32] + b[hd:hd+32]
// Thread tile: c4=(t&7)*4 cols, i0=(t>>3)*2 rows. float4 x/W loads.
// If TRANS, writes transposed into out[kk*64 + j] (no bias-row layout change).
template<bool TRANS>
__device__ __forceinline__
void proj_head(const float* __restrict__ W, const float* __restrict__ bias, int hd,
               const float* xs, float* out, int t)
{
    const int c4 = (t & 7) << 2;
    const int i0 = (t >> 3) << 1;
    float a0x=0.f,a0y=0.f,a0z=0.f,a0w=0.f;
    float a1x=0.f,a1y=0.f,a1z=0.f,a1w=0.f;
#pragma unroll 4
    for (int k = 0; k < DIM; k += 4) {
        float4 xa = *(const float4*)&xs[i0 * XS + k];
        float4 xb = *(const float4*)&xs[(i0 + 1) * XS + k];
        float4 w0 = *(const float4*)&W[(k + 0) * DIM + hd + c4];
        float4 w1 = *(const float4*)&W[(k + 1) * DIM + hd + c4];
        float4 w2 = *(const float4*)&W[(k + 2) * DIM + hd + c4];
        float4 w3 = *(const float4*)&W[(k + 3) * DIM + hd + c4];
        a0x += xa.x*w0.x + xa.y*w1.x + xa.z*w2.x + xa.w*w3.x;
        a0y += xa.x*w0.y + xa.y*w1.y + xa.z*w2.y + xa.w*w3.y;
        a0z += xa.x*w0.z + xa.y*w1.z + xa.z*w2.z + xa.w*w3.z;
        a0w += xa.x*w0.w + xa.y*w1.w + xa.z*w2.w + xa.w*w3.w;
        a1x += xb.x*w0.x + xb.y*w1.x + xb.z*w2.x + xb.w*w3.x;
        a1y += xb.x*w0.y + xb.y*w1.y + xb.z*w2.y + xb.w*w3.y;
        a1z += xb.x*w0.z + xb.y*w1.z + xb.z*w2.z + xb.w*w3.z;
        a1w += xb.x*w0.w + xb.y*w1.w + xb.z*w2.w + xb.w*w3.w;
    }
    float4 bb = *(const float4*)&bias[hd + c4];
    a0x += bb.x; a0y += bb.y; a0z += bb.z; a0w += bb.w;
    a1x += bb.x; a1y += bb.y; a1z += bb.z; a1w += bb.w;
    if (TRANS) {
        // out[kk][j], kk = c4.., j = i0..
        out[(c4+0)*64 + i0] = a0x; out[(c4+1)*64 + i0] = a0y;
        out[(c4+2)*64 + i0] = a0z; out[(c4+3)*64 + i0] = a0w;
        out[(c4+0)*64 + i0+1] = a1x; out[(c4+1)*64 + i0+1] = a1y;
        out[(c4+2)*64 + i0+1] = a1z; out[(c4+3)*64 + i0+1] = a1w;
    } else {
        const int st = (TRANS ? 64 : ((&out[0] != nullptr) ? 0 : 0)); (void)st;
    }
    if (!TRANS) {
        // stride passed implicitly: q uses QS, v uses HDIM — handled by caller wrapper
    }
}

// non-transposed variant with explicit stride (q: QS, v: HDIM)
__device__ __forceinline__
void proj_head_n(const float* __restrict__ W, const float* __restrict__ bias, int hd,
                 const float* xs, float* out, int ostride, int t)
{
    const int c4 = (t & 7) << 2;
    const int i0 = (t >> 3) << 1;
    float a0x=0.f,a0y=0.f,a0z=0.f,a0w=0.f;
    float a1x=0.f,a1y=0.f,a1z=0.f,a1w=0.f;
#pragma unroll 4
    for (int k = 0; k < DIM; k += 4) {
        float4 xa = *(const float4*)&xs[i0 * XS + k];
        float4 xb = *(const float4*)&xs[(i0 + 1) * XS + k];
        float4 w0 = *(const float4*)&W[(k + 0) * DIM + hd + c4];
        float4 w1 = *(const float4*)&W[(k + 1) * DIM + hd + c4];
        float4 w2 = *(const float4*)&W[(k + 2) * DIM + hd + c4];
        float4 w3 = *(const float4*)&W[(k + 3) * DIM + hd + c4];
        a0x += xa.x*w0.x + xa.y*w1.x + xa.z*w2.x + xa.w*w3.x;
        a0y += xa.x*w0.y + xa.y*w1.y + xa.z*w2.y + xa.w*w3.y;
        a0z += xa.x*w0.z + xa.y*w1.z + xa.z*w2.z + xa.w*w3.z;
        a0w += xa.x*w0.w + xa.y*w1.w + xa.z*w2.w + xa.w*w3.w;
        a1x += xb.x*w0.x + xb.y*w1.x + xb.z*w2.x + xb.w*w3.x;
        a1y += xb.x*w0.y + xb.y*w1.y + xb.z*w2.y + xb.w*w3.y;
        a1z += xb.x*w0.z + xb.y*w1.z + xb.z*w2.z + xb.w*w3.z;
        a1w += xb.x*w0.w + xb.y*w1.w + xb.z*w2.w + xb.w*w3.w;
    }
    float4 bb = *(const float4*)&bias[hd + c4];
    float4 r0 = make_float4(a0x+bb.x, a0y+bb.y, a0z+bb.z, a0w+bb.w);
    float4 r1 = make_float4(a1x+bb.x, a1y+bb.y, a1z+bb.z, a1w+bb.w);
    *(float4*)&out[i0 * ostride + c4]       = r0;
    *(float4*)&out[(i0 + 1) * ostride + c4] = r1;
}

__global__ __launch_bounds__(256, 2)
void autoint_kernel(const float* __restrict__ x,
                    const float* __restrict__ Wq, const float* __restrict__ bq,
                    const float* __restrict__ Wk, const float* __restrict__ bk,
                    const float* __restrict__ Wv, const float* __restrict__ bv,
                    const float* __restrict__ W1, const float* __restrict__ b1,
                    const float* __restrict__ W2, const float* __restrict__ b2,
                    float* __restrict__ out)
{
    extern __shared__ float sm[];
    float* xs  = sm;                   // 64*260
    float* qh  = xs + NFEAT * XS;      // 64*36
    float* kt  = qh + NFEAT * QS;      // 32*64 (reused as zh 64*32)
    float* vh  = kt + 2048;            // 64*32
    float* att = vh + 2048;            // 64*68
    float* red = att + NFEAT * ATS;    // 256

    const int t = threadIdx.x;
    const int b = blockIdx.x;
    const float* xg = x + (size_t)b * (NFEAT * DIM);

    // ---- load x ----
    {
        const float4* xg4 = (const float4*)xg;
#pragma unroll
        for (int n = t; n < NFEAT * DIM / 4; n += 256) {
            float4 v = xg4[n];
            *(float4*)&xs[(n >> 6) * XS + ((n & 63) << 2)] = v;
        }
    }
    __syncthreads();

    const float inv_sqrt_d = 0.17677669529663687f; // 1/sqrt(32)

    float facc[16][4];
#pragma unroll
    for (int r = 0; r < 16; r++) { facc[r][0]=0.f; facc[r][1]=0.f; facc[r][2]=0.f; facc[r][3]=0.f; }

    for (int h = 0; h < NHEAD; h++) {
        const int hd = h * HDIM;

        // ---- per-head projections: qh, kt (transposed), vh ----
        proj_head_n(Wq, bq, hd, xs, qh, QS, t);
        proj_head<true>(Wk, bk, hd, xs, kt, t);
        proj_head_n(Wv, bv, hd, xs, vh, HDIM, t);
        __syncthreads();

        // ---- scores: att[i][j] = (q_h[i] . k_h[j]) / sqrt(32) ----
        {
            const int i0 = (t >> 4) << 2;
            const int j0 = (t & 15) << 2;
            float4 a0 = make_float4(0.f,0.f,0.f,0.f);
            float4 a1 = a0, a2 = a0, a3 = a0;
#pragma unroll
            for (int kk = 0; kk < HDIM; kk += 4) {
                float4 k0 = *(const float4*)&kt[(kk+0)*64 + j0];
                float4 k1 = *(const float4*)&kt[(kk+1)*64 + j0];
                float4 k2 = *(const float4*)&kt[(kk+2)*64 + j0];
                float4 k3 = *(const float4*)&kt[(kk+3)*64 + j0];
                float4 q0 = *(const float4*)&qh[(i0+0)*QS + kk];
                float4 q1 = *(const float4*)&qh[(i0+1)*QS + kk];
                float4 q2 = *(const float4*)&qh[(i0+2)*QS + kk];
                float4 q3 = *(const float4*)&qh[(i0+3)*QS + kk];
                a0.x += q0.x*k0.x + q0.y*k1.x + q0.z*k2.x + q0.w*k3.x;
                a0.y += q0.x*k0.y + q0.y*k1.y + q0.z*k2.y + q0.w*k3.y;
                a0.z += q0.x*k0.z + q0.y*k1.z + q0.z*k2.z + q0.w*k3.z;
                a0.w += q0.x*k0.w + q0.y*k1.w + q0.z*k2.w + q0.w*k3.w;
                a1.x += q1.x*k0.x + q1.y*k1.x + q1.z*k2.x + q1.w*k3.x;
                a1.y += q1.x*k0.y + q1.y*k1.y + q1.z*k2.y + q1.w*k3.y;
                a1.z += q1.x*k0.z + q1.y*k1.z + q1.z*k2.z + q1.w*k3.z;
                a1.w += q1.x*k0.w + q1.y*k1.w + q1.z*k2.w + q1.w*k3.w;
                a2.x += q2.x*k0.x + q2.y*k1.x + q2.z*k2.x + q2.w*k3.x;
                a2.y += q2.x*k0.y + q2.y*k1.y + q2.z*k2.y + q2.w*k3.y;
                a2.z += q2.x*k0.z + q2.y*k1.z + q2.z*k2.z + q2.w*k3.z;
                a2.w += q2.x*k0.w + q2.y*k1.w + q2.z*k2.w + q2.w*k3.w;
                a3.x += q3.x*k0.x + q3.y*k1.x + q3.z*k2.x + q3.w*k3.x;
                a3.y += q3.x*k0.y + q3.y*k1.y + q3.z*k2.y + q3.w*k3.y;
                a3.z += q3.x*k0.z + q3.y*k1.z + q3.z*k2.z + q3.w*k3.z;
                a3.w += q3.x*k0.w + q3.y*k1.w + q3.z*k2.w + q3.w*k3.w;
            }
            a0.x*=inv_sqrt_d; a0.y*=inv_sqrt_d; a0.z*=inv_sqrt_d; a0.w*=inv_sqrt_d;
            a1.x*=inv_sqrt_d; a1.y*=inv_sqrt_d; a1.z*=inv_sqrt_d; a1.w*=inv_sqrt_d;
            a2.x*=inv_sqrt_d; a2.y*=inv_sqrt_d; a2.z*=inv_sqrt_d; a2.w*=inv_sqrt_d;
            a3.x*=inv_sqrt_d; a3.y*=inv_sqrt_d; a3.z*=inv_sqrt_d; a3.w*=inv_sqrt_d;
            *(float4*)&att[(i0+0)*ATS + j0] = a0;
            *(float4*)&att[(i0+1)*ATS + j0] = a1;
            *(float4*)&att[(i0+2)*ATS + j0] = a2;
            *(float4*)&att[(i0+3)*ATS + j0] = a3;
        }
        __syncthreads();

        // ---- softmax (row per thread, t < 64) ----
        if (t < NFEAT) {
            float* row = att + t * ATS;
            float m = row[0];
#pragma unroll
            for (int j = 1; j < NFEAT; j++) m = fmaxf(m, row[j]);
            float s = 0.f;
#pragma unroll
            for (int j = 0; j < NFEAT; j++) { float e = __expf(row[j] - m); row[j] = e; s += e; }
            float inv = 1.f / s;
#pragma unroll
            for (int j = 0; j < NFEAT; j++) row[j] *= inv;
        }
        __syncthreads();

        // ---- z head: zh = att @ vh (zh reuses kt) ----
        float* zh = kt;
        {
            const int c4 = (t & 7) << 2;
            const int i0 = (t >> 3) << 1;
            float4 a0 = make_float4(0.f,0.f,0.f,0.f);
            float4 a1 = a0;
#pragma unroll 4
            for (int j = 0; j < NFEAT; j += 4) {
                float4 p0 = *(const float4*)&att[i0 * ATS + j];
                float4 p1 = *(const float4*)&att[(i0+1) * ATS + j];
                float4 v0 = *(const float4*)&vh[(j+0)*HDIM + c4];
                float4 v1 = *(const float4*)&vh[(j+1)*HDIM + c4];
                float4 v2 = *(const float4*)&vh[(j+2)*HDIM + c4];
                float4 v3 = *(const float4*)&vh[(j+3)*HDIM + c4];
                a0.x += p0.x*v0.x + p0.y*v1.x + p0.z*v2.x + p0.w*v3.x;
                a0.y += p0.x*v0.y + p0.y*v1.y + p0.z*v2.y + p0.w*v3.y;
                a0.z += p0.x*v0.z + p0.y*v1.z + p0.z*v2.z + p0.w*v3.z;
                a0.w += p0.x*v0.w + p0.y*v1.w + p0.z*v2.w + p0.w*v3.w;
                a1.x += p1.x*v0.x + p1.y*v1.x + p1.z*v2.x + p1.w*v3.x;
                a1.y += p1.x*v0.y + p1.y*v1.y + p1.z*v2.y + p1.w*v3.y;
                a1.z += p1.x*v0.z + p1.y*v1.z + p1.z*v2.z + p1.w*v3.z;
                a1.w += p1.x*v0.w + p1.y*v1.w + p1.z*v2.w + p1.w*v3.w;
            }
            __syncthreads();  // everyone done READING kt (scores) before zh write
            *(float4*)&zh[i0 * HDIM + c4]     = a0;
            *(float4*)&zh[(i0+1) * HDIM + c4] = a1;
        }
        __syncthreads();

        // ---- facc += z_h @ W1[hd:hd+32, :] ----
        {
            const int jg = t & 63;
            const int i0 = (t >> 6) << 4;
            const float4* W14 = (const float4*)W1;
#pragma unroll
            for (int kk = 0; kk < HDIM; kk += 4) {
                float4 w0 = W14[((hd+kk+0) << 6) + jg];
                float4 w1 = W14[((hd+kk+1) << 6) + jg];
                float4 w2 = W14[((hd+kk+2) << 6) + jg];
                float4 w3 = W14[((hd+kk+3) << 6) + jg];
#pragma unroll
                for (int r = 0; r < 16; r++) {
                    float4 zv = *(const float4*)&zh[(i0+r) * HDIM + kk];
                    facc[r][0] += zv.x*w0.x + zv.y*w1.x + zv.z*w2.x + zv.w*w3.x;
                    facc[r][1] += zv.x*w0.y + zv.y*w1.y + zv.z*w2.y + zv.w*w3.y;
                    facc[r][2] += zv.x*w0.z + zv.y*w1.z + zv.z*w2.z + zv.w*w3.z;
                    facc[r][3] += zv.x*w0.w + zv.y*w1.w + zv.z*w2.w + zv.w*w3.w;
                }
            }
        }
        __syncthreads();  // protect zh/qh/vh before next head rewrites them
    }

    // ---- f = relu(facc + b1 + x); partial dot with W2 ----
    {
        const int jg = t & 63;
        const int i0 = (t >> 6) << 4;
        const int j0 = jg << 2;
        float4 b1v = ((const float4*)b1)[jg];
        float part = 0.f;
#pragma unroll
        for (int r = 0; r < 16; r++) {
            int i = i0 + r;
            float4 w2 = ((const float4*)W2)[(i << 6) + jg];
            float4 xv = *(const float4*)&xs[i * XS + j0];
            float f0 = fmaxf(facc[r][0] + b1v.x + xv.x, 0.f);
            float f1 = fmaxf(facc[r][1] + b1v.y + xv.y, 0.f);
            float f2 = fmaxf(facc[r][2] + b1v.z + xv.z, 0.f);
            float f3 = fmaxf(facc[r][3] + b1v.w + xv.w, 0.f);
            part += f0*w2.x + f1*w2.y + f2*w2.z + f3*w2.w;
        }
        red[t] = part;
    }
    __syncthreads();

#pragma unroll
    for (int s = 128; s > 0; s >>= 1) {
        if (t < s) red[t] += red[t + s];
        __syncthreads();
    }
    if (t == 0) {
        out[b] = 1.f / (1.f + __expf(-(red[0] + b2[0])));
    }
}

extern "C" void kernel_launch(void* const* d_in, const int* in_sizes, int n_in,
                              void* d_out, int out_size)
{
    const float* x  = (const float*)d_in[0];
    const float* Wq = (const float*)d_in[1];
    const float* bq = (const float*)d_in[2];
    const float* Wk = (const float*)d_in[3];
    const float* bk = (const float*)d_in[4];
    const float* Wv = (const float*)d_in[5];
    const float* bv = (const float*)d_in[6];
    const float* W1 = (const float*)d_in[7];
    const float* b1 = (const float*)d_in[8];
    const float* W2 = (const float*)d_in[9];
    const float* b2 = (const float*)d_in[10];
    float* out = (float*)d_out;

    const int smem_bytes = SMEM_FLOATS * (int)sizeof(float); // 110,592 B -> 2 CTAs/SM
    cudaFuncSetAttribute(autoint_kernel,
                         cudaFuncAttributeMaxDynamicSharedMemorySize, smem_bytes);

    autoint_kernel<<<8192, 256, smem_bytes>>>(x, Wq, bq, Wk, bk, Wv, bv,
                                              W1, b1, W2, b2, out);
}

// round 3
// speedup vs baseline: 1.2011x; 1.0615x over previous
#include <cuda_runtime.h>
#include <math.h>

#define NFEAT 64
#define DIM   256
#define NHEAD 8
#define HDIM  32
#define XS    260   // padded x row stride (floats)
#define QS    36    // qh row stride
#define ATS   68    // att row stride

// smem floats:
//  xs  64*260 = 16640
//  qh  64*36  =  2304
//  kt  32*64  =  2048   (k transposed; reused as zh 64*32)
//  vh  64*32  =  2048
//  att 64*68  =  4352
//  red          256
#define SMEM_FLOATS (NFEAT*XS + NFEAT*QS + 2048 + 2048 + NFEAT*ATS + 256)

__global__ __launch_bounds__(256, 2)
void autoint_kernel(const float* __restrict__ x,
                    const float* __restrict__ Wq, const float* __restrict__ bq,
                    const float* __restrict__ Wk, const float* __restrict__ bk,
                    const float* __restrict__ Wv, const float* __restrict__ bv,
                    const float* __restrict__ W1, const float* __restrict__ b1,
                    const float* __restrict__ W2, const float* __restrict__ b2,
                    float* __restrict__ out)
{
    extern __shared__ float sm[];
    float* xs  = sm;                   // 64*260
    float* qh  = xs + NFEAT * XS;      // 64*36
    float* kt  = qh + NFEAT * QS;      // 32*64 (reused as zh 64*32)
    float* vh  = kt + 2048;            // 64*32
    float* att = vh + 2048;            // 64*68
    float* red = att + NFEAT * ATS;    // 256

    const int t = threadIdx.x;
    const int b = blockIdx.x;
    const float* xg = x + (size_t)b * (NFEAT * DIM);

    // ---- load x ----
    {
        const float4* xg4 = (const float4*)xg;
#pragma unroll
        for (int n = t; n < NFEAT * DIM / 4; n += 256) {
            float4 v = xg4[n];
            *(float4*)&xs[(n >> 6) * XS + ((n & 63) << 2)] = v;
        }
    }
    __syncthreads();

    const float inv_sqrt_d = 0.17677669529663687f; // 1/sqrt(32)

    float facc[16][4];
#pragma unroll
    for (int r = 0; r < 16; r++) { facc[r][0]=0.f; facc[r][1]=0.f; facc[r][2]=0.f; facc[r][3]=0.f; }

    for (int h = 0; h < NHEAD; h++) {
        const int hd = h * HDIM;

        // ==== fused q/k/v head projections ====
        // thread tile: 4 rows (i0) x 2 cols (c2) x 3 matrices.
        // One set of x loads (broadcast across 16 col-lanes) feeds 96 FMAs.
        {
            const int c2 = (t & 15) << 1;
            const int i0 = (t >> 4) << 2;
            float aq[4][2], ak[4][2], av[4][2];
#pragma unroll
            for (int r = 0; r < 4; r++) {
                aq[r][0]=0.f; aq[r][1]=0.f;
                ak[r][0]=0.f; ak[r][1]=0.f;
                av[r][0]=0.f; av[r][1]=0.f;
            }
            const int wofs = hd + c2;
#pragma unroll 2
            for (int k = 0; k < DIM; k += 4) {
                float4 x0 = *(const float4*)&xs[(i0+0)*XS + k];
                float4 x1 = *(const float4*)&xs[(i0+1)*XS + k];
                float4 x2 = *(const float4*)&xs[(i0+2)*XS + k];
                float4 x3 = *(const float4*)&xs[(i0+3)*XS + k];

                float2 wq0 = *(const float2*)&Wq[(k+0)*DIM + wofs];
                float2 wq1 = *(const float2*)&Wq[(k+1)*DIM + wofs];
                float2 wq2 = *(const float2*)&Wq[(k+2)*DIM + wofs];
                float2 wq3 = *(const float2*)&Wq[(k+3)*DIM + wofs];
                float2 wk0 = *(const float2*)&Wk[(k+0)*DIM + wofs];
                float2 wk1 = *(const float2*)&Wk[(k+1)*DIM + wofs];
                float2 wk2 = *(const float2*)&Wk[(k+2)*DIM + wofs];
                float2 wk3 = *(const float2*)&Wk[(k+3)*DIM + wofs];
                float2 wv0 = *(const float2*)&Wv[(k+0)*DIM + wofs];
                float2 wv1 = *(const float2*)&Wv[(k+1)*DIM + wofs];
                float2 wv2 = *(const float2*)&Wv[(k+2)*DIM + wofs];
                float2 wv3 = *(const float2*)&Wv[(k+3)*DIM + wofs];

#pragma unroll
                for (int r = 0; r < 4; r++) {
                    float4 xr = (r==0) ? x0 : (r==1) ? x1 : (r==2) ? x2 : x3;
                    aq[r][0] += xr.x*wq0.x + xr.y*wq1.x + xr.z*wq2.x + xr.w*wq3.x;
                    aq[r][1] += xr.x*wq0.y + xr.y*wq1.y + xr.z*wq2.y + xr.w*wq3.y;
                    ak[r][0] += xr.x*wk0.x + xr.y*wk1.x + xr.z*wk2.x + xr.w*wk3.x;
                    ak[r][1] += xr.x*wk0.y + xr.y*wk1.y + xr.z*wk2.y + xr.w*wk3.y;
                    av[r][0] += xr.x*wv0.x + xr.y*wv1.x + xr.z*wv2.x + xr.w*wv3.x;
                    av[r][1] += xr.x*wv0.y + xr.y*wv1.y + xr.z*wv2.y + xr.w*wv3.y;
                }
            }
            float2 bbq = *(const float2*)&bq[wofs];
            float2 bbk = *(const float2*)&bk[wofs];
            float2 bbv = *(const float2*)&bv[wofs];
            // q: row-major [64 x QS]
#pragma unroll
            for (int r = 0; r < 4; r++) {
                *(float2*)&qh[(i0+r)*QS + c2] =
                    make_float2(aq[r][0] + bbq.x, aq[r][1] + bbq.y);
                *(float2*)&vh[(i0+r)*HDIM + c2] =
                    make_float2(av[r][0] + bbv.x, av[r][1] + bbv.y);
            }
            // k transposed: kt[kk][j]; 4 consecutive rows -> float4 store per col
            *(float4*)&kt[(c2+0)*64 + i0] = make_float4(
                ak[0][0]+bbk.x, ak[1][0]+bbk.x, ak[2][0]+bbk.x, ak[3][0]+bbk.x);
            *(float4*)&kt[(c2+1)*64 + i0] = make_float4(
                ak[0][1]+bbk.y, ak[1][1]+bbk.y, ak[2][1]+bbk.y, ak[3][1]+bbk.y);
        }
        __syncthreads();

        // ---- scores: att[i][j] = (q_h[i] . k_h[j]) / sqrt(32) ----
        {
            const int i0 = (t >> 4) << 2;
            const int j0 = (t & 15) << 2;
            float4 a0 = make_float4(0.f,0.f,0.f,0.f);
            float4 a1 = a0, a2 = a0, a3 = a0;
#pragma unroll
            for (int kk = 0; kk < HDIM; kk += 4) {
                float4 k0 = *(const float4*)&kt[(kk+0)*64 + j0];
                float4 k1 = *(const float4*)&kt[(kk+1)*64 + j0];
                float4 k2 = *(const float4*)&kt[(kk+2)*64 + j0];
                float4 k3 = *(const float4*)&kt[(kk+3)*64 + j0];
                float4 q0 = *(const float4*)&qh[(i0+0)*QS + kk];
                float4 q1 = *(const float4*)&qh[(i0+1)*QS + kk];
                float4 q2 = *(const float4*)&qh[(i0+2)*QS + kk];
                float4 q3 = *(const float4*)&qh[(i0+3)*QS + kk];
                a0.x += q0.x*k0.x + q0.y*k1.x + q0.z*k2.x + q0.w*k3.x;
                a0.y += q0.x*k0.y + q0.y*k1.y + q0.z*k2.y + q0.w*k3.y;
                a0.z += q0.x*k0.z + q0.y*k1.z + q0.z*k2.z + q0.w*k3.z;
                a0.w += q0.x*k0.w + q0.y*k1.w + q0.z*k2.w + q0.w*k3.w;
                a1.x += q1.x*k0.x + q1.y*k1.x + q1.z*k2.x + q1.w*k3.x;
                a1.y += q1.x*k0.y + q1.y*k1.y + q1.z*k2.y + q1.w*k3.y;
                a1.z += q1.x*k0.z + q1.y*k1.z + q1.z*k2.z + q1.w*k3.z;
                a1.w += q1.x*k0.w + q1.y*k1.w + q1.z*k2.w + q1.w*k3.w;
                a2.x += q2.x*k0.x + q2.y*k1.x + q2.z*k2.x + q2.w*k3.x;
                a2.y += q2.x*k0.y + q2.y*k1.y + q2.z*k2.y + q2.w*k3.y;
                a2.z += q2.x*k0.z + q2.y*k1.z + q2.z*k2.z + q2.w*k3.z;
                a2.w += q2.x*k0.w + q2.y*k1.w + q2.z*k2.w + q2.w*k3.w;
                a3.x += q3.x*k0.x + q3.y*k1.x + q3.z*k2.x + q3.w*k3.x;
                a3.y += q3.x*k0.y + q3.y*k1.y + q3.z*k2.y + q3.w*k3.y;
                a3.z += q3.x*k0.z + q3.y*k1.z + q3.z*k2.z + q3.w*k3.z;
                a3.w += q3.x*k0.w + q3.y*k1.w + q3.z*k2.w + q3.w*k3.w;
            }
            a0.x*=inv_sqrt_d; a0.y*=inv_sqrt_d; a0.z*=inv_sqrt_d; a0.w*=inv_sqrt_d;
            a1.x*=inv_sqrt_d; a1.y*=inv_sqrt_d; a1.z*=inv_sqrt_d; a1.w*=inv_sqrt_d;
            a2.x*=inv_sqrt_d; a2.y*=inv_sqrt_d; a2.z*=inv_sqrt_d; a2.w*=inv_sqrt_d;
            a3.x*=inv_sqrt_d; a3.y*=inv_sqrt_d; a3.z*=inv_sqrt_d; a3.w*=inv_sqrt_d;
            *(float4*)&att[(i0+0)*ATS + j0] = a0;
            *(float4*)&att[(i0+1)*ATS + j0] = a1;
            *(float4*)&att[(i0+2)*ATS + j0] = a2;
            *(float4*)&att[(i0+3)*ATS + j0] = a3;
        }
        __syncthreads();

        // ---- softmax: 2 threads per row (halves combined via shfl with lane^1) ----
        if (t < 128) {
            const int row  = t >> 1;
            const int half = (t & 1) << 5;   // 0 or 32
            float* rp = att + row * ATS + half;
            float m = rp[0];
#pragma unroll
            for (int j = 1; j < 32; j++) m = fmaxf(m, rp[j]);
            m = fmaxf(m, __shfl_xor_sync(0xFFFFFFFF, m, 1));
            float s = 0.f;
#pragma unroll
            for (int j = 0; j < 32; j++) { float e = __expf(rp[j] - m); rp[j] = e; s += e; }
            s += __shfl_xor_sync(0xFFFFFFFF, s, 1);
            float inv = 1.f / s;
#pragma unroll
            for (int j = 0; j < 32; j++) rp[j] *= inv;
        }
        __syncthreads();

        // ---- z head: zh = att @ vh (zh reuses kt) ----
        float* zh = kt;
        {
            const int c4 = (t & 7) << 2;
            const int i0 = (t >> 3) << 1;
            float4 a0 = make_float4(0.f,0.f,0.f,0.f);
            float4 a1 = a0;
#pragma unroll 4
            for (int j = 0; j < NFEAT; j += 4) {
                float4 p0 = *(const float4*)&att[i0 * ATS + j];
                float4 p1 = *(const float4*)&att[(i0+1) * ATS + j];
                float4 v0 = *(const float4*)&vh[(j+0)*HDIM + c4];
                float4 v1 = *(const float4*)&vh[(j+1)*HDIM + c4];
                float4 v2 = *(const float4*)&vh[(j+2)*HDIM + c4];
                float4 v3 = *(const float4*)&vh[(j+3)*HDIM + c4];
                a0.x += p0.x*v0.x + p0.y*v1.x + p0.z*v2.x + p0.w*v3.x;
                a0.y += p0.x*v0.y + p0.y*v1.y + p0.z*v2.y + p0.w*v3.y;
                a0.z += p0.x*v0.z + p0.y*v1.z + p0.z*v2.z + p0.w*v3.z;
                a0.w += p0.x*v0.w + p0.y*v1.w + p0.z*v2.w + p0.w*v3.w;
                a1.x += p1.x*v0.x + p1.y*v1.x + p1.z*v2.x + p1.w*v3.x;
                a1.y += p1.x*v0.y + p1.y*v1.y + p1.z*v2.y + p1.w*v3.y;
                a1.z += p1.x*v0.z + p1.y*v1.z + p1.z*v2.z + p1.w*v3.z;
                a1.w += p1.x*v0.w + p1.y*v1.w + p1.z*v2.w + p1.w*v3.w;
            }
            __syncthreads();  // everyone done READING kt (k data) before zh write
            *(float4*)&zh[i0 * HDIM + c4]     = a0;
            *(float4*)&zh[(i0+1) * HDIM + c4] = a1;
        }
        __syncthreads();

        // ---- facc += z_h @ W1[hd:hd+32, :] ----
        {
            const int jg = t & 63;
            const int i0 = (t >> 6) << 4;
            const float4* W14 = (const float4*)W1;
#pragma unroll
            for (int kk = 0; kk < HDIM; kk += 4) {
                float4 w0 = W14[((hd+kk+0) << 6) + jg];
                float4 w1 = W14[((hd+kk+1) << 6) + jg];
                float4 w2 = W14[((hd+kk+2) << 6) + jg];
                float4 w3 = W14[((hd+kk+3) << 6) + jg];
#pragma unroll
                for (int r = 0; r < 16; r++) {
                    float4 zv = *(const float4*)&zh[(i0+r) * HDIM + kk];
                    facc[r][0] += zv.x*w0.x + zv.y*w1.x + zv.z*w2.x + zv.w*w3.x;
                    facc[r][1] += zv.x*w0.y + zv.y*w1.y + zv.z*w2.y + zv.w*w3.y;
                    facc[r][2] += zv.x*w0.z + zv.y*w1.z + zv.z*w2.z + zv.w*w3.z;
                    facc[r][3] += zv.x*w0.w + zv.y*w1.w + zv.z*w2.w + zv.w*w3.w;
                }
            }
        }
        __syncthreads();  // protect zh/qh/vh before next head rewrites them
    }

    // ---- f = relu(facc + b1 + x); partial dot with W2 ----
    {
        const int jg = t & 63;
        const int i0 = (t >> 6) << 4;
        const int j0 = jg << 2;
        float4 b1v = ((const float4*)b1)[jg];
        float part = 0.f;
#pragma unroll
        for (int r = 0; r < 16; r++) {
            int i = i0 + r;
            float4 w2 = ((const float4*)W2)[(i << 6) + jg];
            float4 xv = *(const float4*)&xs[i * XS + j0];
            float f0 = fmaxf(facc[r][0] + b1v.x + xv.x, 0.f);
            float f1 = fmaxf(facc[r][1] + b1v.y + xv.y, 0.f);
            float f2 = fmaxf(facc[r][2] + b1v.z + xv.z, 0.f);
            float f3 = fmaxf(facc[r][3] + b1v.w + xv.w, 0.f);
            part += f0*w2.x + f1*w2.y + f2*w2.z + f3*w2.w;
        }
        red[t] = part;
    }
    __syncthreads();

#pragma unroll
    for (int s = 128; s > 0; s >>= 1) {
        if (t < s) red[t] += red[t + s];
        __syncthreads();
    }
    if (t == 0) {
        out[b] = 1.f / (1.f + __expf(-(red[0] + b2[0])));
    }
}

extern "C" void kernel_launch(void* const* d_in, const int* in_sizes, int n_in,
                              void* d_out, int out_size)
{
    const float* x  = (const float*)d_in[0];
    const float* Wq = (const float*)d_in[1];
    const float* bq = (const float*)d_in[2];
    const float* Wk = (const float*)d_in[3];
    const float* bk = (const float*)d_in[4];
    const float* Wv = (const float*)d_in[5];
    const float* bv = (const float*)d_in[6];
    const float* W1 = (const float*)d_in[7];
    const float* b1 = (const float*)d_in[8];
    const float* W2 = (const float*)d_in[9];
    const float* b2 = (const float*)d_in[10];
    float* out = (float*)d_out;

    const int smem_bytes = SMEM_FLOATS * (int)sizeof(float); // 110,592 B -> 2 CTAs/SM
    cudaFuncSetAttribute(autoint_kernel,
                         cudaFuncAttributeMaxDynamicSharedMemorySize, smem_bytes);

    autoint_kernel<<<8192, 256, smem_bytes>>>(x, Wq, bq, Wk, bk, Wv, bv,
                                              W1, b1, W2, b2, out);
}

// round 4
// speedup vs baseline: 1.5465x; 1.2876x over previous
#include <cuda_runtime.h>
#include <math.h>

#define NFEAT 64
#define DIM   256
#define NHEAD 8
#define HDIM  32
#define XS    260   // padded x row stride (floats)
#define QS    36    // qh row stride
#define ATS   68    // att row stride

#define SMEM_FLOATS (NFEAT*XS + NFEAT*QS + 2048 + 2048 + NFEAT*ATS + 256)

typedef unsigned long long u64;

// packed dual-fp32 FMA: d = a*b + d (elementwise on 2 lanes)
__device__ __forceinline__ void ffma2(u64& d, u64 a, u64 b) {
    asm("fma.rn.f32x2 %0, %1, %2, %0;" : "+l"(d) : "l"(a), "l"(b));
}
__device__ __forceinline__ u64 dup2(float v) {
    u64 r; asm("mov.b64 %0, {%1, %1};" : "=l"(r) : "f"(v)); return r;
}
__device__ __forceinline__ float2 unpk(u64 v) {
    float lo, hi; asm("mov.b64 {%0, %1}, %2;" : "=f"(lo), "=f"(hi) : "l"(v));
    return make_float2(lo, hi);
}

__global__ __launch_bounds__(256, 2)
void autoint_kernel(const float* __restrict__ x,
                    const float* __restrict__ Wq, const float* __restrict__ bq,
                    const float* __restrict__ Wk, const float* __restrict__ bk,
                    const float* __restrict__ Wv, const float* __restrict__ bv,
                    const float* __restrict__ W1, const float* __restrict__ b1,
                    const float* __restrict__ W2, const float* __restrict__ b2,
                    float* __restrict__ out)
{
    extern __shared__ float sm[];
    float* xs  = sm;                   // 64*260
    float* qh  = xs + NFEAT * XS;      // 64*36
    float* kt  = qh + NFEAT * QS;      // 32*64 (k transposed; reused as zh 64*32)
    float* vh  = kt + 2048;            // 64*32
    float* att = vh + 2048;            // 64*68
    float* red = att + NFEAT * ATS;    // 256

    const int t = threadIdx.x;
    const int b = blockIdx.x;
    const float* xg = x + (size_t)b * (NFEAT * DIM);

    // ---- load x ----
    {
        const float4* xg4 = (const float4*)xg;
#pragma unroll
        for (int n = t; n < NFEAT * DIM / 4; n += 256) {
            float4 v = xg4[n];
            *(float4*)&xs[(n >> 6) * XS + ((n & 63) << 2)] = v;
        }
    }
    __syncthreads();

    const float inv_sqrt_d = 0.17677669529663687f; // 1/sqrt(32)

    // facc: 16 rows x 4 cols as 16x2 packed pairs
    u64 facc[16][2];
#pragma unroll
    for (int r = 0; r < 16; r++) { facc[r][0] = 0ull; facc[r][1] = 0ull; }

    for (int h = 0; h < NHEAD; h++) {
        const int hd = h * HDIM;

        // ==== fused q/k/v head projections (packed f32x2) ====
        // thread tile: 4 rows (i0) x 2 cols (c2, one packed pair) x 3 matrices.
        {
            const int c2 = (t & 15) << 1;
            const int i0 = (t >> 4) << 2;
            u64 aq[4] = {0ull,0ull,0ull,0ull};
            u64 ak[4] = {0ull,0ull,0ull,0ull};
            u64 av[4] = {0ull,0ull,0ull,0ull};
            const int wofs = hd + c2;
#pragma unroll 2
            for (int k = 0; k < DIM; k += 4) {
                float4 x0 = *(const float4*)&xs[(i0+0)*XS + k];
                float4 x1 = *(const float4*)&xs[(i0+1)*XS + k];
                float4 x2 = *(const float4*)&xs[(i0+2)*XS + k];
                float4 x3 = *(const float4*)&xs[(i0+3)*XS + k];

                u64 wq0 = *(const u64*)&Wq[(k+0)*DIM + wofs];
                u64 wq1 = *(const u64*)&Wq[(k+1)*DIM + wofs];
                u64 wq2 = *(const u64*)&Wq[(k+2)*DIM + wofs];
                u64 wq3 = *(const u64*)&Wq[(k+3)*DIM + wofs];
                u64 wk0 = *(const u64*)&Wk[(k+0)*DIM + wofs];
                u64 wk1 = *(const u64*)&Wk[(k+1)*DIM + wofs];
                u64 wk2 = *(const u64*)&Wk[(k+2)*DIM + wofs];
                u64 wk3 = *(const u64*)&Wk[(k+3)*DIM + wofs];
                u64 wv0 = *(const u64*)&Wv[(k+0)*DIM + wofs];
                u64 wv1 = *(const u64*)&Wv[(k+1)*DIM + wofs];
                u64 wv2 = *(const u64*)&Wv[(k+2)*DIM + wofs];
                u64 wv3 = *(const u64*)&Wv[(k+3)*DIM + wofs];

#pragma unroll
                for (int r = 0; r < 4; r++) {
                    float4 xr = (r==0) ? x0 : (r==1) ? x1 : (r==2) ? x2 : x3;
                    u64 d;
                    d = dup2(xr.x); ffma2(aq[r], d, wq0); ffma2(ak[r], d, wk0); ffma2(av[r], d, wv0);
                    d = dup2(xr.y); ffma2(aq[r], d, wq1); ffma2(ak[r], d, wk1); ffma2(av[r], d, wv1);
                    d = dup2(xr.z); ffma2(aq[r], d, wq2); ffma2(ak[r], d, wk2); ffma2(av[r], d, wv2);
                    d = dup2(xr.w); ffma2(aq[r], d, wq3); ffma2(ak[r], d, wk3); ffma2(av[r], d, wv3);
                }
            }
            float2 bbq = *(const float2*)&bq[wofs];
            float2 bbk = *(const float2*)&bk[wofs];
            float2 bbv = *(const float2*)&bv[wofs];
            float2 akr[4];
#pragma unroll
            for (int r = 0; r < 4; r++) {
                float2 q = unpk(aq[r]);
                float2 v = unpk(av[r]);
                akr[r]   = unpk(ak[r]);
                *(float2*)&qh[(i0+r)*QS + c2]   = make_float2(q.x + bbq.x, q.y + bbq.y);
                *(float2*)&vh[(i0+r)*HDIM + c2] = make_float2(v.x + bbv.x, v.y + bbv.y);
            }
            // k transposed: kt[kk][j]
            *(float4*)&kt[(c2+0)*64 + i0] = make_float4(
                akr[0].x+bbk.x, akr[1].x+bbk.x, akr[2].x+bbk.x, akr[3].x+bbk.x);
            *(float4*)&kt[(c2+1)*64 + i0] = make_float4(
                akr[0].y+bbk.y, akr[1].y+bbk.y, akr[2].y+bbk.y, akr[3].y+bbk.y);
        }
        __syncthreads();

        // ---- scores (packed): att[i][j] = (q_h[i] . k_h[j]) / sqrt(32) ----
        {
            const int i0 = (t >> 4) << 2;
            const int j0 = (t & 15) << 2;
            u64 a[4][2];
#pragma unroll
            for (int r = 0; r < 4; r++) { a[r][0] = 0ull; a[r][1] = 0ull; }
#pragma unroll
            for (int kk = 0; kk < HDIM; kk += 4) {
                ulonglong2 k0 = *(const ulonglong2*)&kt[(kk+0)*64 + j0];
                ulonglong2 k1 = *(const ulonglong2*)&kt[(kk+1)*64 + j0];
                ulonglong2 k2 = *(const ulonglong2*)&kt[(kk+2)*64 + j0];
                ulonglong2 k3 = *(const ulonglong2*)&kt[(kk+3)*64 + j0];
                float4 q0 = *(const float4*)&qh[(i0+0)*QS + kk];
                float4 q1 = *(const float4*)&qh[(i0+1)*QS + kk];
                float4 q2 = *(const float4*)&qh[(i0+2)*QS + kk];
                float4 q3 = *(const float4*)&qh[(i0+3)*QS + kk];
#pragma unroll
                for (int r = 0; r < 4; r++) {
                    float4 qr = (r==0) ? q0 : (r==1) ? q1 : (r==2) ? q2 : q3;
                    u64 d;
                    d = dup2(qr.x); ffma2(a[r][0], d, k0.x); ffma2(a[r][1], d, k0.y);
                    d = dup2(qr.y); ffma2(a[r][0], d, k1.x); ffma2(a[r][1], d, k1.y);
                    d = dup2(qr.z); ffma2(a[r][0], d, k2.x); ffma2(a[r][1], d, k2.y);
                    d = dup2(qr.w); ffma2(a[r][0], d, k3.x); ffma2(a[r][1], d, k3.y);
                }
            }
#pragma unroll
            for (int r = 0; r < 4; r++) {
                float2 lo = unpk(a[r][0]);
                float2 hi = unpk(a[r][1]);
                *(float4*)&att[(i0+r)*ATS + j0] = make_float4(
                    lo.x*inv_sqrt_d, lo.y*inv_sqrt_d, hi.x*inv_sqrt_d, hi.y*inv_sqrt_d);
            }
        }
        __syncthreads();

        // ---- softmax: 2 threads per row ----
        if (t < 128) {
            const int row  = t >> 1;
            const int half = (t & 1) << 5;
            float* rp = att + row * ATS + half;
            float m = rp[0];
#pragma unroll
            for (int j = 1; j < 32; j++) m = fmaxf(m, rp[j]);
            m = fmaxf(m, __shfl_xor_sync(0xFFFFFFFF, m, 1));
            float s = 0.f;
#pragma unroll
            for (int j = 0; j < 32; j++) { float e = __expf(rp[j] - m); rp[j] = e; s += e; }
            s += __shfl_xor_sync(0xFFFFFFFF, s, 1);
            float inv = 1.f / s;
#pragma unroll
            for (int j = 0; j < 32; j++) rp[j] *= inv;
        }
        __syncthreads();

        // ---- z head (packed): zh = att @ vh (zh reuses kt) ----
        float* zh = kt;
        {
            const int c4 = (t & 7) << 2;
            const int i0 = (t >> 3) << 1;
            u64 a0[2] = {0ull, 0ull};
            u64 a1[2] = {0ull, 0ull};
#pragma unroll 4
            for (int j = 0; j < NFEAT; j += 4) {
                float4 p0 = *(const float4*)&att[i0 * ATS + j];
                float4 p1 = *(const float4*)&att[(i0+1) * ATS + j];
                ulonglong2 v0 = *(const ulonglong2*)&vh[(j+0)*HDIM + c4];
                ulonglong2 v1 = *(const ulonglong2*)&vh[(j+1)*HDIM + c4];
                ulonglong2 v2 = *(const ulonglong2*)&vh[(j+2)*HDIM + c4];
                ulonglong2 v3 = *(const ulonglong2*)&vh[(j+3)*HDIM + c4];
                u64 d;
                d = dup2(p0.x); ffma2(a0[0], d, v0.x); ffma2(a0[1], d, v0.y);
                d = dup2(p0.y); ffma2(a0[0], d, v1.x); ffma2(a0[1], d, v1.y);
                d = dup2(p0.z); ffma2(a0[0], d, v2.x); ffma2(a0[1], d, v2.y);
                d = dup2(p0.w); ffma2(a0[0], d, v3.x); ffma2(a0[1], d, v3.y);
                d = dup2(p1.x); ffma2(a1[0], d, v0.x); ffma2(a1[1], d, v0.y);
                d = dup2(p1.y); ffma2(a1[0], d, v1.x); ffma2(a1[1], d, v1.y);
                d = dup2(p1.z); ffma2(a1[0], d, v2.x); ffma2(a1[1], d, v2.y);
                d = dup2(p1.w); ffma2(a1[0], d, v3.x); ffma2(a1[1], d, v3.y);
            }
            __syncthreads();  // everyone done READING kt (k data) before zh write
            float2 a0lo = unpk(a0[0]), a0hi = unpk(a0[1]);
            float2 a1lo = unpk(a1[0]), a1hi = unpk(a1[1]);
            *(float4*)&zh[i0 * HDIM + c4]     = make_float4(a0lo.x, a0lo.y, a0hi.x, a0hi.y);
            *(float4*)&zh[(i0+1) * HDIM + c4] = make_float4(a1lo.x, a1lo.y, a1hi.x, a1hi.y);
        }
        __syncthreads();

        // ---- facc += z_h @ W1[hd:hd+32, :] (packed) ----
        {
            const int jg = t & 63;
            const int i0 = (t >> 6) << 4;
            const float4* W14 = (const float4*)W1;
#pragma unroll
            for (int kk = 0; kk < HDIM; kk += 4) {
                ulonglong2 w0 = *(const ulonglong2*)&W14[((hd+kk+0) << 6) + jg];
                ulonglong2 w1 = *(const ulonglong2*)&W14[((hd+kk+1) << 6) + jg];
                ulonglong2 w2 = *(const ulonglong2*)&W14[((hd+kk+2) << 6) + jg];
                ulonglong2 w3 = *(const ulonglong2*)&W14[((hd+kk+3) << 6) + jg];
#pragma unroll
                for (int r = 0; r < 16; r++) {
                    float4 zv = *(const float4*)&zh[(i0+r) * HDIM + kk];
                    u64 d;
                    d = dup2(zv.x); ffma2(facc[r][0], d, w0.x); ffma2(facc[r][1], d, w0.y);
                    d = dup2(zv.y); ffma2(facc[r][0], d, w1.x); ffma2(facc[r][1], d, w1.y);
                    d = dup2(zv.z); ffma2(facc[r][0], d, w2.x); ffma2(facc[r][1], d, w2.y);
                    d = dup2(zv.w); ffma2(facc[r][0], d, w3.x); ffma2(facc[r][1], d, w3.y);
                }
            }
        }
        __syncthreads();  // protect zh/qh/vh before next head rewrites them
    }

    // ---- f = relu(facc + b1 + x); partial dot with W2 ----
    {
        const int jg = t & 63;
        const int i0 = (t >> 6) << 4;
        const int j0 = jg << 2;
        float4 b1v = ((const float4*)b1)[jg];
        float part = 0.f;
#pragma unroll
        for (int r = 0; r < 16; r++) {
            int i = i0 + r;
            float4 w2 = ((const float4*)W2)[(i << 6) + jg];
            float4 xv = *(const float4*)&xs[i * XS + j0];
            float2 flo = unpk(facc[r][0]);
            float2 fhi = unpk(facc[r][1]);
            float f0 = fmaxf(flo.x + b1v.x + xv.x, 0.f);
            float f1 = fmaxf(flo.y + b1v.y + xv.y, 0.f);
            float f2 = fmaxf(fhi.x + b1v.z + xv.z, 0.f);
            float f3 = fmaxf(fhi.y + b1v.w + xv.w, 0.f);
            part += f0*w2.x + f1*w2.y + f2*w2.z + f3*w2.w;
        }
        red[t] = part;
    }
    __syncthreads();

#pragma unroll
    for (int s = 128; s > 0; s >>= 1) {
        if (t < s) red[t] += red[t + s];
        __syncthreads();
    }
    if (t == 0) {
        out[b] = 1.f / (1.f + __expf(-(red[0] + b2[0])));
    }
}

extern "C" void kernel_launch(void* const* d_in, const int* in_sizes, int n_in,
                              void* d_out, int out_size)
{
    const float* x  = (const float*)d_in[0];
    const float* Wq = (const float*)d_in[1];
    const float* bq = (const float*)d_in[2];
    const float* Wk = (const float*)d_in[3];
    const float* bk = (const float*)d_in[4];
    const float* Wv = (const float*)d_in[5];
    const float* bv = (const float*)d_in[6];
    const float* W1 = (const float*)d_in[7];
    const float* b1 = (const float*)d_in[8];
    const float* W2 = (const float*)d_in[9];
    const float* b2 = (const float*)d_in[10];
    float* out = (float*)d_out;

    const int smem_bytes = SMEM_FLOATS * (int)sizeof(float); // 110,592 B -> 2 CTAs/SM
    cudaFuncSetAttribute(autoint_kernel,
                         cudaFuncAttributeMaxDynamicSharedMemorySize, smem_bytes);

    autoint_kernel<<<8192, 256, smem_bytes>>>(x, Wq, bq, Wk, bk, Wv, bv,
                                              W1, b1, W2, b2, out);
}